// round 15
// baseline (speedup 1.0000x reference)
#include <cuda_runtime.h>
#include <cuda_bf16.h>
#include <math.h>
#include <stdint.h>

#define N_CLASS 32000
#define NH      1024
#define ENC     512
#define DEC     256

// ---------------- scratch (no allocations allowed) ----------------
__device__ float g_xw_enc[ENC * NH];
__device__ float g_enc_out[ENC * NH];
__device__ float g_enc_outT[NH * ENC];                 // transposed copy for ctx GEMM
__device__ float g_A[ENC * NH];
__device__ float g_xw_dec[DEC * NH];
__device__ float g_hcat[DEC * 2 * NH];                 // [h | ctx] rows
__device__ float g_S[DEC * ENC];                       // raw scores
__device__ float g_W[DEC * ENC];                       // softmax weights
__device__ float g_h0[NH];
__device__ float g_zeros[NH];                          // never written: zero bias
__device__ float g_part[8 * 512 * 1024];               // split-K partials (16MB)
__device__ unsigned long long g_hbuf_enc[2][NH];       // {tag<<32 | value} packets
__device__ unsigned long long g_hbuf_dec[2][NH];

// zero tag buffers EVERY launch (graph replays would reuse stale tags)
__global__ void init_kernel(const float* __restrict__ hidden) {
    int i = blockIdx.x * blockDim.x + threadIdx.x;
    if (i < NH) g_h0[i] = hidden[i];
    if (i < 2 * NH) {
        (&g_hbuf_enc[0][0])[i] = 0ULL;
        (&g_hbuf_dec[0][0])[i] = 0ULL;
    }
}

// ---------------- small helpers ----------------
__device__ __forceinline__ float tanh_fast(float x) {
    float e = __expf(2.f * x);
    return 1.f - 2.f / (e + 1.f);
}
__device__ __forceinline__ unsigned su32(const void* p) {
    return (unsigned)__cvta_generic_to_shared(p);
}
// tagged publish/poll: scalar ALIGNED b64 packet {tag(hi), value(lo)} — single-copy atomic
__device__ __forceinline__ void pub_tag(unsigned long long* p, float v, int tag) {
    unsigned long long pkt = ((unsigned long long)(unsigned)tag << 32)
                           | (unsigned long long)__float_as_uint(v);
    asm volatile("st.relaxed.gpu.global.b64 [%0], %1;" :: "l"(p), "l"(pkt) : "memory");
}
// dual poll: both independent loads in flight per retry -> one round trip, not two
__device__ __forceinline__ void poll_tag2(const unsigned long long* p0,
                                          const unsigned long long* p1,
                                          int tag, float& v0, float& v1) {
    unsigned long long a, b;
    const unsigned ut = (unsigned)tag;
    do {
        asm volatile("ld.relaxed.gpu.global.b64 %0, [%1];" : "=l"(a) : "l"(p0) : "memory");
        asm volatile("ld.relaxed.gpu.global.b64 %0, [%1];" : "=l"(b) : "l"(p1) : "memory");
    } while ((unsigned)(a >> 32) != ut || (unsigned)(b >> 32) != ut);
    v0 = __uint_as_float((unsigned)a);
    v1 = __uint_as_float((unsigned)b);
}

// ---------------- warp-MMA primitives (generic PTX -> HMMA) ----------------
__device__ __forceinline__ void ldm_x4(unsigned* r, unsigned addr) {
    asm volatile("ldmatrix.sync.aligned.m8n8.x4.shared.b16 {%0,%1,%2,%3}, [%4];"
                 : "=r"(r[0]), "=r"(r[1]), "=r"(r[2]), "=r"(r[3]) : "r"(addr));
}
__device__ __forceinline__ void ldm_x2(unsigned* r, unsigned addr) {
    asm volatile("ldmatrix.sync.aligned.m8n8.x2.shared.b16 {%0,%1}, [%2];"
                 : "=r"(r[0]), "=r"(r[1]) : "r"(addr));
}
__device__ __forceinline__ void mma_bf16(float* d, const unsigned* a, const unsigned* b) {
    asm volatile("mma.sync.aligned.m16n8k16.row.col.f32.bf16.bf16.f32 "
                 "{%0,%1,%2,%3}, {%4,%5,%6,%7}, {%8,%9}, {%0,%1,%2,%3};"
                 : "+f"(d[0]), "+f"(d[1]), "+f"(d[2]), "+f"(d[3])
                 : "r"(a[0]), "r"(a[1]), "r"(a[2]), "r"(a[3]), "r"(b[0]), "r"(b[1]));
}

// ---------------- bf16-split tensor GEMM: 128x64 tile, 2 CTAs/SM ----------------
#define BK        64
#define PADH      72
#define A_TILE_B  (128 * PADH * 2)       // 18432
#define B_TILE_B  (64 * PADH * 2)        // 9216
#define STAGE_B   (2 * A_TILE_B + 2 * B_TILE_B)   // 55296
#define GEMM_SMEM (2 * STAGE_B)          // 110592 -> 2 CTAs/SM

// load NR rows x 64 fp32 (NR*16 float4 over 256 threads)
template<int NR>
__device__ __forceinline__ void ldg_tile(
    const float* __restrict__ src, int ld, int row0, long col0, int tid, float4* v)
{
    #pragma unroll
    for (int i = 0; i < NR / 16; i++) {
        int j = tid + 256 * i;
        int r = j >> 4, c = j & 15;
        v[i] = *(const float4*)(src + (size_t)(row0 + r) * ld + col0 + c * 4);
    }
}

template<int NR>
__device__ __forceinline__ void sts_tile_split(
    const float4* v, unsigned dst_hi, unsigned dst_lo, int tid)
{
    #pragma unroll
    for (int i = 0; i < NR / 16; i++) {
        int j = tid + 256 * i;
        int r = j >> 4, c = j & 15;
        float4 t = v[i];
        __nv_bfloat162 h0 = __floats2bfloat162_rn(t.x, t.y);
        __nv_bfloat162 h1 = __floats2bfloat162_rn(t.z, t.w);
        float lx = t.x - __bfloat162float(h0.x);
        float ly = t.y - __bfloat162float(h0.y);
        float lz = t.z - __bfloat162float(h1.x);
        float lw = t.w - __bfloat162float(h1.y);
        __nv_bfloat162 l0 = __floats2bfloat162_rn(lx, ly);
        __nv_bfloat162 l1 = __floats2bfloat162_rn(lz, lw);
        unsigned boff = (unsigned)(r * PADH + c * 4) * 2;
        unsigned long long hv = ((unsigned long long)(*(unsigned*)&h1) << 32) | (*(unsigned*)&h0);
        unsigned long long lv = ((unsigned long long)(*(unsigned*)&l1) << 32) | (*(unsigned*)&l0);
        asm volatile("st.shared.b64 [%0], %1;" :: "r"(dst_hi + boff), "l"(hv) : "memory");
        asm volatile("st.shared.b64 [%0], %1;" :: "r"(dst_lo + boff), "l"(lv) : "memory");
    }
}

extern __shared__ unsigned char gemm_dyn[];

__global__ void __launch_bounds__(256, 2) gemm_mma(
    const float* __restrict__ Am, const float* __restrict__ Bm,
    const float* __restrict__ bias, float* __restrict__ Cdirect,
    float* __restrict__ partial,
    int M, int N, int lda, int ldb, int ldc,
    int kt_per_split, int kt_total)
{
    const unsigned sbase = su32(gemm_dyn);
    const int tid  = threadIdx.x;
    const int wid  = tid >> 5;
    const int lane = tid & 31;
    const int n0 = blockIdx.x * 64;
    const int m0 = blockIdx.y * 128;
    const int s  = blockIdx.z;
    const long kt0 = (long)s * kt_per_split;
    int nt_ = kt_total - (int)kt0;
    if (nt_ > kt_per_split) nt_ = kt_per_split;
    const int ntiles = nt_;

    const int wr = wid & 3;      // M group of 32 (0..3)
    const int wc = wid >> 2;     // N group of 32 (0..1)

    float acc[2][4][4];
    #pragma unroll
    for (int mt = 0; mt < 2; mt++)
        #pragma unroll
        for (int nt = 0; nt < 4; nt++)
            #pragma unroll
            for (int q = 0; q < 4; q++) acc[mt][nt][q] = 0.f;

    const int arow = wr * 32 + (lane & 15);
    const int acolh = (lane >> 4) * 8;
    const int brow = wc * 32 + (lane & 7);
    const int bcolh = ((lane >> 3) & 1) * 8;

    float4 va[8], vb[4];
    ldg_tile<128>(Am, lda, m0, kt0 * BK, tid, va);
    ldg_tile<64>(Bm, ldb, n0, kt0 * BK, tid, vb);

    for (int kt = 0; kt < ntiles; kt++) {
        const unsigned bb = sbase + (unsigned)(kt & 1) * STAGE_B;
        const unsigned Ah = bb, Al = bb + A_TILE_B;
        const unsigned Bh = bb + 2 * A_TILE_B, Bl = bb + 2 * A_TILE_B + B_TILE_B;

        sts_tile_split<128>(va, Ah, Al, tid);
        sts_tile_split<64>(vb, Bh, Bl, tid);
        __syncthreads();

        if (kt + 1 < ntiles) {
            long c0 = (kt0 + kt + 1) * BK;
            ldg_tile<128>(Am, lda, m0, c0, tid, va);
            ldg_tile<64>(Bm, ldb, n0, c0, tid, vb);
        }

        #pragma unroll
        for (int kk = 0; kk < 4; kk++) {
            unsigned a_hi[2][4], a_lo[2][4], b_hi[4][2], b_lo[4][2];
            #pragma unroll
            for (int mt = 0; mt < 2; mt++) {
                unsigned off = (unsigned)((arow + mt * 16) * PADH + kk * 16 + acolh) * 2;
                ldm_x4(a_hi[mt], Ah + off);
                ldm_x4(a_lo[mt], Al + off);
            }
            #pragma unroll
            for (int nt = 0; nt < 4; nt++) {
                unsigned off = (unsigned)((brow + nt * 8) * PADH + kk * 16 + bcolh) * 2;
                ldm_x2(b_hi[nt], Bh + off);
                ldm_x2(b_lo[nt], Bl + off);
            }
            #pragma unroll
            for (int mt = 0; mt < 2; mt++)
                #pragma unroll
                for (int nt = 0; nt < 4; nt++) {
                    mma_bf16(acc[mt][nt], a_hi[mt], b_hi[nt]);
                    mma_bf16(acc[mt][nt], a_hi[mt], b_lo[nt]);
                    mma_bf16(acc[mt][nt], a_lo[mt], b_hi[nt]);
                }
        }
    }

    const int g   = lane >> 2;
    const int tig = lane & 3;
    if (gridDim.z == 1) {
        #pragma unroll
        for (int mt = 0; mt < 2; mt++) {
            int row = m0 + wr * 32 + mt * 16 + g;
            #pragma unroll
            for (int nt = 0; nt < 4; nt++) {
                int col = n0 + wc * 32 + nt * 8 + tig * 2;
                float b0 = bias[col], b1 = bias[col + 1];
                float2 v0 = {acc[mt][nt][0] + b0, acc[mt][nt][1] + b1};
                float2 v1 = {acc[mt][nt][2] + b0, acc[mt][nt][3] + b1};
                *(float2*)&Cdirect[(size_t)row * ldc + col] = v0;
                *(float2*)&Cdirect[(size_t)(row + 8) * ldc + col] = v1;
            }
        }
    } else {
        #pragma unroll
        for (int mt = 0; mt < 2; mt++) {
            int row = m0 + wr * 32 + mt * 16 + g;
            float* pp = partial + ((size_t)s * M + row) * N;
            #pragma unroll
            for (int nt = 0; nt < 4; nt++) {
                int col = n0 + wc * 32 + nt * 8 + tig * 2;
                float2 v0 = {acc[mt][nt][0], acc[mt][nt][1]};
                float2 v1 = {acc[mt][nt][2], acc[mt][nt][3]};
                *(float2*)&pp[col] = v0;
                *(float2*)&pp[(size_t)8 * N + col] = v1;
            }
        }
    }
}

__global__ void reduce_splitk(const float* __restrict__ part,
                              const float* __restrict__ bias,
                              float* __restrict__ C, int MN, int N, int S)
{
    int i = blockIdx.x * 256 + threadIdx.x;
    if (i >= MN) return;
    float a = bias[i & (N - 1)];
    for (int s = 0; s < S; s++) a += part[(size_t)s * MN + i];
    C[i] = a;
}

// ---------------- encoder scan: 2-row h-reuse, dual-poll ----------------
__global__ void __launch_bounds__(512, 1) enc_scan_kernel(
    const float* __restrict__ Whh, const float* __restrict__ bhh)
{
    __shared__ float sh[NH];
    const int c    = blockIdx.x;
    const int tid  = threadIdx.x;
    const int p    = tid >> 5;
    const int lane = tid & 31;
    const int r0   = c * 32 + 2 * p;
    const int r1   = r0 + 1;

    float w0[32], w1[32];
    {
        const float* wp0 = Whh + (size_t)r0 * NH + lane * 32;
        const float* wp1 = Whh + (size_t)r1 * NH + lane * 32;
        #pragma unroll
        for (int j = 0; j < 8; j++) {
            int off = ((j + lane) & 7) * 4;
            #pragma unroll
            for (int k = 0; k < 4; k++) {
                w0[4*j+k] = wp0[off+k];
                w1[4*j+k] = wp1[off+k];
            }
        }
    }
    const float b0 = bhh[r0], b1 = bhh[r1];

    for (int t = 0; t < ENC; t++) {
        float xw0 = 0.f, xw1 = 0.f;
        if (lane == 0)  xw0 = __ldcg(&g_xw_enc[(size_t)t * NH + r0]);
        if (lane == 16) xw1 = __ldcg(&g_xw_enc[(size_t)t * NH + r1]);

        if (t == 0) {
            if (tid < 256) *(float4*)&sh[tid * 4] = __ldcg((const float4*)g_h0 + tid);
        } else {
            const unsigned long long* src = g_hbuf_enc[(t - 1) & 1];
            float v0, v1;
            poll_tag2(src + tid, src + tid + 512, t, v0, v1);
            sh[tid] = v0; sh[tid + 512] = v1;
        }
        __syncthreads();

        const float* shp = &sh[lane * 32];
        float a0 = 0.f, a1 = 0.f;
        #pragma unroll
        for (int j = 0; j < 8; j++) {
            float4 hv = *(const float4*)&shp[((j + lane) & 7) * 4];
            a0 = fmaf(w0[4*j+0], hv.x, a0); a1 = fmaf(w1[4*j+0], hv.x, a1);
            a0 = fmaf(w0[4*j+1], hv.y, a0); a1 = fmaf(w1[4*j+1], hv.y, a1);
            a0 = fmaf(w0[4*j+2], hv.z, a0); a1 = fmaf(w1[4*j+2], hv.z, a1);
            a0 = fmaf(w0[4*j+3], hv.w, a0); a1 = fmaf(w1[4*j+3], hv.w, a1);
        }
        #pragma unroll
        for (int o = 16; o > 0; o >>= 1) {
            a0 += __shfl_xor_sync(0xffffffffu, a0, o);
            a1 += __shfl_xor_sync(0xffffffffu, a1, o);
        }

        if (lane == 0) {
            float h = tanh_fast(a0 + xw0 + b0);
            pub_tag(&g_hbuf_enc[t & 1][r0], h, t + 1);
            g_enc_out[(size_t)t * NH + r0]  = h;
            g_enc_outT[(size_t)r0 * ENC + t] = h;
        }
        if (lane == 16) {
            float h = tanh_fast(a1 + xw1 + b1);
            pub_tag(&g_hbuf_enc[t & 1][r1], h, t + 1);
            g_enc_out[(size_t)t * NH + r1]  = h;
            g_enc_outT[(size_t)r1 * ENC + t] = h;
        }
        __syncthreads();
    }
}

// ---------------- decoder scan: PURE h chain (attention hoisted to GEMMs) ----------
__global__ void __launch_bounds__(512, 1) dec_scan_kernel(
    const float* __restrict__ Whh, const float* __restrict__ bhh)
{
    __shared__ float sh[NH];
    const int c    = blockIdx.x;
    const int tid  = threadIdx.x;
    const int p    = tid >> 5;
    const int lane = tid & 31;
    const int r0   = c * 32 + 2 * p;
    const int r1   = r0 + 1;

    float w0[32], w1[32];
    {
        const float* wp0 = Whh + (size_t)r0 * NH + lane * 32;
        const float* wp1 = Whh + (size_t)r1 * NH + lane * 32;
        #pragma unroll
        for (int j = 0; j < 8; j++) {
            int off = ((j + lane) & 7) * 4;
            #pragma unroll
            for (int k = 0; k < 4; k++) {
                w0[4*j+k] = wp0[off+k];
                w1[4*j+k] = wp1[off+k];
            }
        }
    }
    const float b0 = bhh[r0], b1 = bhh[r1];

    for (int t = 0; t < DEC; t++) {
        float xw0 = 0.f, xw1 = 0.f;
        if (lane == 0)  xw0 = __ldcg(&g_xw_dec[(size_t)t * NH + r0]);
        if (lane == 16) xw1 = __ldcg(&g_xw_dec[(size_t)t * NH + r1]);

        if (t == 0) {
            if (tid < 256)
                *(float4*)&sh[tid * 4] =
                    __ldcg((const float4*)(g_enc_out + (size_t)(ENC - 1) * NH) + tid);
        } else {
            const unsigned long long* src = g_hbuf_dec[(t - 1) & 1];
            float v0, v1;
            poll_tag2(src + tid, src + tid + 512, t, v0, v1);
            sh[tid] = v0; sh[tid + 512] = v1;
        }
        __syncthreads();

        const float* shp = &sh[lane * 32];
        float a0 = 0.f, a1 = 0.f;
        #pragma unroll
        for (int j = 0; j < 8; j++) {
            float4 hv = *(const float4*)&shp[((j + lane) & 7) * 4];
            a0 = fmaf(w0[4*j+0], hv.x, a0); a1 = fmaf(w1[4*j+0], hv.x, a1);
            a0 = fmaf(w0[4*j+1], hv.y, a0); a1 = fmaf(w1[4*j+1], hv.y, a1);
            a0 = fmaf(w0[4*j+2], hv.z, a0); a1 = fmaf(w1[4*j+2], hv.z, a1);
            a0 = fmaf(w0[4*j+3], hv.w, a0); a1 = fmaf(w1[4*j+3], hv.w, a1);
        }
        #pragma unroll
        for (int o = 16; o > 0; o >>= 1) {
            a0 += __shfl_xor_sync(0xffffffffu, a0, o);
            a1 += __shfl_xor_sync(0xffffffffu, a1, o);
        }

        if (lane == 0) {
            float h = tanh_fast(a0 + xw0 + b0);
            pub_tag(&g_hbuf_dec[t & 1][r0], h, t + 1);
            g_hcat[(size_t)t * 2 * NH + r0] = h;
        }
        if (lane == 16) {
            float h = tanh_fast(a1 + xw1 + b1);
            pub_tag(&g_hbuf_dec[t & 1][r1], h, t + 1);
            g_hcat[(size_t)t * 2 * NH + r1] = h;
        }
        __syncthreads();
    }
}

// ---------------- batched row softmax over S[256,512] ----------------
__global__ void __launch_bounds__(512) softmax_kernel(float* __restrict__ attns)
{
    __shared__ float red[16];
    __shared__ float bc[2];
    const int t = blockIdx.x, tid = threadIdx.x, warp = tid >> 5, lane = tid & 31;

    float sc = g_S[(size_t)t * ENC + tid];
    float mx = sc;
    #pragma unroll
    for (int o = 16; o > 0; o >>= 1) mx = fmaxf(mx, __shfl_xor_sync(0xffffffffu, mx, o));
    if (lane == 0) red[warp] = mx;
    __syncthreads();
    if (tid < 16) {
        float v = red[tid];
        #pragma unroll
        for (int o = 8; o > 0; o >>= 1) v = fmaxf(v, __shfl_xor_sync(0xffffu, v, o));
        if (tid == 0) bc[0] = v;
    }
    __syncthreads();
    float e = __expf(sc - bc[0]);
    float sm = e;
    #pragma unroll
    for (int o = 16; o > 0; o >>= 1) sm += __shfl_xor_sync(0xffffffffu, sm, o);
    if (lane == 0) red[warp] = sm;
    __syncthreads();
    if (tid < 16) {
        float v = red[tid];
        #pragma unroll
        for (int o = 8; o > 0; o >>= 1) v += __shfl_xor_sync(0xffffu, v, o);
        if (tid == 0) bc[1] = v;
    }
    __syncthreads();
    float w = e / bc[1];
    g_W[(size_t)t * ENC + tid] = w;
    attns[(size_t)t * ENC + tid] = w;
}

// ---------------- launch ----------------
extern "C" void kernel_launch(void* const* d_in, const int* in_sizes, int n_in,
                              void* d_out, int out_size)
{
    const float* enc_input = (const float*)d_in[0];
    const float* hidden    = (const float*)d_in[1];
    const float* dec_input = (const float*)d_in[2];
    const float* enc_W_ih  = (const float*)d_in[3];
    const float* enc_W_hh  = (const float*)d_in[4];
    const float* enc_b_ih  = (const float*)d_in[5];
    const float* enc_b_hh  = (const float*)d_in[6];
    const float* dec_W_ih  = (const float*)d_in[7];
    const float* dec_W_hh  = (const float*)d_in[8];
    const float* dec_b_ih  = (const float*)d_in[9];
    const float* dec_b_hh  = (const float*)d_in[10];
    const float* attn_W    = (const float*)d_in[11];
    const float* attn_b    = (const float*)d_in[12];
    const float* out_W     = (const float*)d_in[13];
    const float* out_b     = (const float*)d_in[14];

    float* out   = (float*)d_out;
    float* outs  = out;                              // [256, 32000]
    float* attns = out + (size_t)DEC * N_CLASS;      // [256, 512]

    float *p_xw_enc, *p_enc_out, *p_enc_outT, *p_A, *p_xw_dec, *p_hcat,
          *p_S, *p_W, *p_part, *p_zeros;
    cudaGetSymbolAddress((void**)&p_xw_enc, g_xw_enc);
    cudaGetSymbolAddress((void**)&p_enc_out, g_enc_out);
    cudaGetSymbolAddress((void**)&p_enc_outT, g_enc_outT);
    cudaGetSymbolAddress((void**)&p_A, g_A);
    cudaGetSymbolAddress((void**)&p_xw_dec, g_xw_dec);
    cudaGetSymbolAddress((void**)&p_hcat, g_hcat);
    cudaGetSymbolAddress((void**)&p_S, g_S);
    cudaGetSymbolAddress((void**)&p_W, g_W);
    cudaGetSymbolAddress((void**)&p_part, g_part);
    cudaGetSymbolAddress((void**)&p_zeros, g_zeros);

    cudaFuncSetAttribute(gemm_mma,
                         cudaFuncAttributeMaxDynamicSharedMemorySize, GEMM_SMEM);

    init_kernel<<<8, 256>>>(hidden);

    // enc_xw : M=512,N=1024,K=32000, split 4
    gemm_mma<<<dim3(16, 4, 4), 256, GEMM_SMEM>>>(
        enc_input, enc_W_ih, nullptr, nullptr, p_part,
        ENC, NH, N_CLASS, N_CLASS, 0, 125, 500);
    reduce_splitk<<<(ENC * NH) / 256, 256>>>(p_part, enc_b_ih, p_xw_enc, ENC * NH, NH, 4);

    // dec_xw : M=256,N=1024,K=32000, split 8
    gemm_mma<<<dim3(16, 2, 8), 256, GEMM_SMEM>>>(
        dec_input, dec_W_ih, nullptr, nullptr, p_part,
        DEC, NH, N_CLASS, N_CLASS, 0, 63, 500);
    reduce_splitk<<<(DEC * NH) / 256, 256>>>(p_part, dec_b_ih, p_xw_dec, DEC * NH, NH, 8);

    // encoder scan (writes g_enc_out + g_enc_outT)
    enc_scan_kernel<<<32, 512>>>(enc_W_hh, enc_b_hh);

    // A = enc_out @ attn_W^T + b : M=512,N=1024,K=1024 direct
    gemm_mma<<<dim3(16, 4, 1), 256, GEMM_SMEM>>>(
        p_enc_out, attn_W, attn_b, p_A, nullptr,
        ENC, NH, NH, NH, NH, 16, 16);

    // decoder scan: pure h chain -> g_hcat[:, :NH]
    dec_scan_kernel<<<32, 512>>>(dec_W_hh, dec_b_hh);

    // S = H @ A^T : M=256,N=512,K=1024 (A rows = g_hcat stride 2048)
    gemm_mma<<<dim3(8, 2, 1), 256, GEMM_SMEM>>>(
        p_hcat, p_A, p_zeros, p_S, nullptr,
        DEC, ENC, 2 * NH, NH, ENC, 16, 16);

    // row softmax -> g_W + attns
    softmax_kernel<<<DEC, 512>>>(attns);

    // ctx = W @ enc_out : M=256,N=1024,K=512 (B = enc_outT), C into g_hcat[:, NH:]
    gemm_mma<<<dim3(16, 2, 1), 256, GEMM_SMEM>>>(
        p_W, p_enc_outT, p_zeros, p_hcat + NH, nullptr,
        DEC, NH, ENC, ENC, 2 * NH, 8, 8);

    // outs = hcat @ out_W^T + out_b : M=256,N=32000,K=2048 direct
    gemm_mma<<<dim3(500, 2, 1), 256, GEMM_SMEM>>>(
        p_hcat, out_W, out_b, outs, nullptr,
        DEC, N_CLASS, 2 * NH, 2 * NH, N_CLASS, 32, 32);
}